// round 7
// baseline (speedup 1.0000x reference)
#include <cuda_runtime.h>
#include <cuda_bf16.h>
#include <cstddef>

#define COL   4096
#define TPB   512
#define NW    (TPB/32)     // 16 warps
#define RPB   8            // rows per block, software-pipelined

__global__ __launch_bounds__(TPB, 2) void layernorm_v2_kernel(
    const float* __restrict__ x,
    const float* __restrict__ alpha,
    const float* __restrict__ beta,
    float* __restrict__ out)
{
    __shared__ float wsum[2][NW];   // parity double-buffered
    __shared__ float ws0[2][NW];
    __shared__ float ws1[2][NW];
    __shared__ float wc2[NW];       // per-warp constant Cw = sum of r^2

    const int tid  = threadIdx.x;
    const int lane = tid & 31;
    const int wid  = tid >> 5;

    const int f4a = 2 * tid;
    const int f4b = 2 * tid + 1;

    // reciprocals 1/(i+1) for this thread's 8 fixed positions (once per block)
    const int e0 = 8 * tid;
    const float r0x = 1.0f / (float)(e0 + 1);
    const float r0y = 1.0f / (float)(e0 + 2);
    const float r0z = 1.0f / (float)(e0 + 3);
    const float r0w = 1.0f / (float)(e0 + 4);
    const float r1x = 1.0f / (float)(e0 + 5);
    const float r1y = 1.0f / (float)(e0 + 6);
    const float r1z = 1.0f / (float)(e0 + 7);
    const float r1w = 1.0f / (float)(e0 + 8);
    const float C = ((r0x * r0x + r0y * r0y) + (r0z * r0z + r0w * r0w))
                  + ((r1x * r1x + r1y * r1y) + (r1z * r1z + r1w * r1w));

    // per-warp Cw (block-lifetime constant), published once
    {
        float cw = C;
        #pragma unroll
        for (int o = 16; o > 0; o >>= 1) cw += __shfl_xor_sync(0xffffffffu, cw, o);
        if (lane == 0) wc2[wid] = cw;
    }

    const float al = __ldg(alpha);
    const float be = __ldg(beta);

    const size_t row0 = (size_t)blockIdx.x * RPB;

    // prologue: load first row
    float4 a0 = ((const float4*)(x + row0 * COL))[f4a];
    float4 a1 = ((const float4*)(x + row0 * COL))[f4b];

    __syncthreads();   // covers wc2 publication (block-start only)

    // local copy of the 16 per-warp constants would cost regs; read smem in loop.

    #pragma unroll 1
    for (int k = 0; k < RPB; ++k) {
        const int buf = k & 1;

        // prefetch next row before the barrier (LDG issue crosses BAR.SYNC)
        float4 b0, b1;
        if (k + 1 < RPB) {
            const float* xn = x + (row0 + k + 1) * COL;
            b0 = ((const float4*)xn)[f4a];
            b1 = ((const float4*)xn)[f4b];
        }

        // local inclusive scan of the 8-chunk
        const float p0 = a0.x;
        const float p1 = p0 + a0.y;
        const float p2 = p1 + a0.z;
        const float p3 = p2 + a0.w;
        const float p4 = p3 + a1.x;
        const float p5 = p4 + a1.y;
        const float p6 = p5 + a1.z;
        const float p7 = p6 + a1.w;
        const float tot = p7;

        // warp inclusive scan of thread totals, interleaved with q_i math
        float v = tot;
        float sv = __shfl_up_sync(0xffffffffu, v, 1);
        if (lane >= 1) v += sv;
        const float q0 = a0.x - p0 * r0x;
        const float q1 = a0.y - p1 * r0y;
        sv = __shfl_up_sync(0xffffffffu, v, 2);
        if (lane >= 2) v += sv;
        const float q2 = a0.z - p2 * r0z;
        const float q3 = a0.w - p3 * r0w;
        sv = __shfl_up_sync(0xffffffffu, v, 4);
        if (lane >= 4) v += sv;
        const float q4 = a1.x - p4 * r1x;
        const float q5 = a1.y - p5 * r1y;
        sv = __shfl_up_sync(0xffffffffu, v, 8);
        if (lane >= 8) v += sv;
        const float q6 = a1.z - p6 * r1z;
        const float q7 = a1.w - p7 * r1w;
        sv = __shfl_up_sync(0xffffffffu, v, 16);
        if (lane >= 16) v += sv;

        const float l = v - tot;   // warp-local exclusive prefix

        const float A = ((q0 * q0 + q1 * q1) + (q2 * q2 + q3 * q3))
                      + ((q4 * q4 + q5 * q5) + (q6 * q6 + q7 * q7));
        const float B = ((q0 * r0x + q1 * r0y) + (q2 * r0z + q3 * r0w))
                      + ((q4 * r1x + q5 * r1y) + (q6 * r1z + q7 * r1w));

        // per-thread factored terms
        float t0 = A - 2.0f * l * B + l * l * C;   // constant part
        float t1 = 2.0f * l * C - 2.0f * B;        // coefficient of W_w

        // warp-reduce t0,t1 (two independent shfl chains)
        #pragma unroll
        for (int o = 16; o > 0; o >>= 1) {
            t0 += __shfl_xor_sync(0xffffffffu, t0, o);
            t1 += __shfl_xor_sync(0xffffffffu, t1, o);
        }

        if (lane == 31) wsum[buf][wid] = v;     // warp total
        if (lane == 0)  { ws0[buf][wid] = t0; ws1[buf][wid] = t1; }
        __syncthreads();                        // THE one barrier per row

        // every thread redundantly: scan warp sums + accumulate variance
        float W = 0.0f, varsum = 0.0f;
        #pragma unroll
        for (int w = 0; w < NW; ++w) {
            const float swv = wsum[buf][w];
            varsum += ws0[buf][w] + W * (ws1[buf][w] + W * wc2[w]);
            W += swv;
        }

        const float var   = varsum * (1.0f / (float)(COL - 1));
        const float mean  = W * (1.0f / (float)COL);
        const float scale = al * rsqrtf(var + 1e-5f);
        const float shift = be - mean * scale;      // out = x*scale + shift

        float* orow = out + (row0 + k) * COL;
        float4 o4;
        o4.x = a0.x * scale + shift;
        o4.y = a0.y * scale + shift;
        o4.z = a0.z * scale + shift;
        o4.w = a0.w * scale + shift;
        ((float4*)orow)[f4a] = o4;
        o4.x = a1.x * scale + shift;
        o4.y = a1.y * scale + shift;
        o4.z = a1.z * scale + shift;
        o4.w = a1.w * scale + shift;
        ((float4*)orow)[f4b] = o4;

        a0 = b0;
        a1 = b1;
    }
}

extern "C" void kernel_launch(void* const* d_in, const int* in_sizes, int n_in,
                              void* d_out, int out_size)
{
    const float* x     = (const float*)d_in[0];
    const float* alpha = (const float*)d_in[1];
    const float* beta  = (const float*)d_in[2];
    float*       out   = (float*)d_out;

    const int rows = in_sizes[0] / COL;
    const int grid = rows / RPB;               // 4096 blocks x 8 rows

    layernorm_v2_kernel<<<grid, TPB>>>(x, alpha, beta, out);
}